// round 11
// baseline (speedup 1.0000x reference)
#include <cuda_runtime.h>
#include <cstdint>

// Output: R[b, s, 64, 64] fp32, 16384 matrices of 16 KB each.
// Per matrix: 32 diagonal 2x2 rotation blocks (128 nonzero floats), zeros
// elsewhere; nonzero locations identical across matrices.
//
// One CTA (256 threads) per matrix. Each thread owns float4 slots
// tid + 256k (k=0..3): 4 unconditional coalesced zero stores plus at most
// one predicated (sin,cos)-pair overwrite to the same address (same-thread
// program order). Stores are st.global.wt (write-through): the output is a
// write-once stream, so lines never go dirty in L2 — no writeback pass,
// DRAM writes scheduled at store time in address order.

static constexpr unsigned THREADS = 256;

static __device__ __forceinline__ void stwt_v4(float4* p, float4 v) {
    asm volatile(
        "st.global.wt.v4.f32 [%0], {%1, %2, %3, %4};"
        :: "l"(p), "f"(v.x), "f"(v.y), "f"(v.z), "f"(v.w)
        : "memory");
}

__global__ void __launch_bounds__(THREADS) rope2d_wt_kernel(
    const float* __restrict__ spa,   // (n_mat, 2)
    float4* __restrict__ out)        // (n_mat, 1024) float4 view
{
    unsigned tid = threadIdx.x;
    unsigned bs  = blockIdx.x;

    // ---- match decode: slot w = tid + 256k -> row = 16k + (tid>>4),
    // f4col = tid & 15. Pair slot iff f4col == 4k + (tid>>6).
    unsigned f4   = tid & 15u;
    int      diff = (int)f4 - (int)(tid >> 6);
    bool   match  = (diff >= 0) && ((diff & 3) == 0);
    unsigned km   = (unsigned)diff >> 2;            // matching k (0..3)
    unsigned row  = 16u * km + (tid >> 4);          // matched output row

    // ---- pair value (meaningful only when match) ---------------------------
    float4 pv = make_float4(0.f, 0.f, 0.f, 0.f);
    if (match) {
        float2 xy = *reinterpret_cast<const float2*>(spa + (size_t)bs * 2u);
        unsigned h = row >> 1;                      // 0..31
        float coord = (h & 16u) ? xy.y : xy.x;
        // inv_freq = 10000^(-(h%16)/16) = 2^(-(h%16)*log2(10000)/16)
        float invf = exp2f(-(float)(h & 15u) * (13.287712379549449f / 16.0f));
        float s, c;
        __sincosf(coord * invf, &s, &c);
        float a, b;
        if (row & 1u) { a = s; b = c;  }            // odd row:  (sin, cos)
        else          { a = c; b = -s; }            // even row: (cos, -sin)
        if (row & 2u) { pv.z = a; pv.w = b; }       // pair at lanes 2,3
        else          { pv.x = a; pv.y = b; }       // pair at lanes 0,1
    }

    // ---- 4 unconditional write-through zero stores + 1 predicated overwrite
    const float4 z = make_float4(0.f, 0.f, 0.f, 0.f);
    float4* base = out + (size_t)bs * 1024u + tid;
    #pragma unroll
    for (unsigned k = 0; k < 4; k++)
        stwt_v4(base + 256u * k, z);
    if (match)
        stwt_v4(base + 256u * km, pv);              // same addr, ordered after zero
}

extern "C" void kernel_launch(void* const* d_in, const int* in_sizes, int n_in,
                              void* d_out, int out_size)
{
    const float* spa = (const float*)d_in[0];
    float4* out = (float4*)d_out;

    unsigned n_mat = (unsigned)(out_size / 4096);   // 16384
    rope2d_wt_kernel<<<n_mat, THREADS>>>(spa, out);
}

// round 12
// speedup vs baseline: 1.0518x; 1.0518x over previous
#include <cuda_runtime.h>
#include <cstdint>

// RotaryEmbedding2D: R[b, s, 64, 64] fp32, 16384 matrices of 16 KB each.
// Per matrix: 32 diagonal 2x2 rotation blocks (128 nonzero floats), zeros
// elsewhere; nonzero locations identical across matrices.
//
// FINAL (round-8 champion form). One CTA (256 threads) per matrix; each
// thread owns float4 slots tid + 256k (k=0..3), with the (sin,cos) pair
// selected in-register for its single matching slot. All stores are
// st.global.cs (evict-first): measured best policy — default LRU loses
// ~1.6us to writeback scheduling, .wt loses ~2.8us to unmerged sectors.
// Kernel is pinned at the path-independent DRAM write ceiling (~6.8 TB/s
// steady-state); verified invariant across TMA-bulk / v4 / v8 store paths.

static constexpr unsigned THREADS = 256;

__global__ void __launch_bounds__(THREADS) rope2d_kernel(
    const float* __restrict__ spa,   // (n_mat, 2)
    float4* __restrict__ out)        // (n_mat, 1024) float4 view
{
    unsigned tid = threadIdx.x;
    unsigned bs  = blockIdx.x;

    // ---- match decode: slot w = tid + 256k -> row = 16k + (tid>>4),
    // f4col = tid & 15. Pair slot iff f4col == 4k + (tid>>6).
    unsigned f4   = tid & 15u;
    int      diff = (int)f4 - (int)(tid >> 6);
    bool   match  = (diff >= 0) && ((diff & 3) == 0);
    unsigned km   = (unsigned)diff >> 2;            // matching k (0..3)
    unsigned row  = 16u * km + (tid >> 4);          // matched output row

    // ---- pair value (zeros when no match) ----------------------------------
    float4 pv = make_float4(0.f, 0.f, 0.f, 0.f);
    if (match) {
        float2 xy = *reinterpret_cast<const float2*>(spa + (size_t)bs * 2u);
        unsigned h = row >> 1;                      // 0..31
        float coord = (h & 16u) ? xy.y : xy.x;
        // inv_freq = 10000^(-(h%16)/16) = 2^(-(h%16)*log2(10000)/16)
        float invf = exp2f(-(float)(h & 15u) * (13.287712379549449f / 16.0f));
        float s, c;
        __sincosf(coord * invf, &s, &c);
        float a, b;
        if (row & 1u) { a = s; b = c;  }            // odd row:  (sin, cos)
        else          { a = c; b = -s; }            // even row: (cos, -sin)
        if (row & 2u) { pv.z = a; pv.w = b; }       // pair at lanes 2,3
        else          { pv.x = a; pv.y = b; }       // pair at lanes 0,1
    }

    // ---- 4 streaming stores, pair value selected in-register ---------------
    const float4 z = make_float4(0.f, 0.f, 0.f, 0.f);
    float4* base = out + (size_t)bs * 1024u + tid;
    #pragma unroll
    for (unsigned k = 0; k < 4; k++) {
        float4 v = (match && k == km) ? pv : z;
        __stcs(base + 256u * k, v);                 // st.global.cs.v4 (evict-first)
    }
}

extern "C" void kernel_launch(void* const* d_in, const int* in_sizes, int n_in,
                              void* d_out, int out_size)
{
    const float* spa = (const float*)d_in[0];
    float4* out = (float4*)d_out;

    unsigned n_mat = (unsigned)(out_size / 4096);   // 16384
    rope2d_kernel<<<n_mat, THREADS>>>(spa, out);
}

// round 13
// speedup vs baseline: 1.0715x; 1.0187x over previous
#include <cuda_runtime.h>
#include <cstdint>

// RotaryEmbedding2D: R[b, s, 64, 64] fp32, 16384 matrices of 16 KB each.
// Per matrix: 32 diagonal 2x2 rotation blocks (128 nonzero floats), zeros
// elsewhere; nonzero locations identical across matrices.
//
// Converged form: one CTA (512 threads) per matrix. Each thread owns float4
// slots tid + 512k (k=0..1): 2 unconditional coalesced zero stores plus at
// most one predicated (sin,cos)-pair overwrite to the same address (same-
// thread program order guarantees the pair lands). All stores st.global.cs
// (evict-first) — measured best policy: default LRU +1.6us (writeback
// scheduling), .wt +2.8us (unmerged sectors). Kernel is pinned at the
// path-independent DRAM write ceiling (~6.8 TB/s steady-state), verified
// invariant across TMA-bulk / STG.v4 / STG.v8 store paths.

static constexpr unsigned THREADS = 512;

__global__ void __launch_bounds__(THREADS) rope2d_kernel(
    const float* __restrict__ spa,   // (n_mat, 2)
    float4* __restrict__ out)        // (n_mat, 1024) float4 view
{
    unsigned tid = threadIdx.x;
    unsigned bs  = blockIdx.x;

    // ---- match decode: slot w = tid + 512k (k=0..1) -> row = 32k + (tid>>4),
    // f4col = tid & 15. Pair slot iff f4col == row>>2 = 8k + (tid>>6).
    int      diff = (int)(tid & 15u) - (int)(tid >> 6);
    bool   match  = (diff == 0) || (diff == 8);
    unsigned km   = (unsigned)diff >> 3;            // matching k (0..1)
    unsigned row  = 32u * km + (tid >> 4);          // matched output row

    // ---- pair value (meaningful only when match) ---------------------------
    float4 pv = make_float4(0.f, 0.f, 0.f, 0.f);
    if (match) {
        float2 xy = *reinterpret_cast<const float2*>(spa + (size_t)bs * 2u);
        unsigned h = row >> 1;                      // 0..31
        float coord = (h & 16u) ? xy.y : xy.x;
        // inv_freq = 10000^(-(h%16)/16) = 2^(-(h%16)*log2(10000)/16)
        float invf = exp2f(-(float)(h & 15u) * (13.287712379549449f / 16.0f));
        float s, c;
        __sincosf(coord * invf, &s, &c);
        float a, b;
        if (row & 1u) { a = s; b = c;  }            // odd row:  (sin, cos)
        else          { a = c; b = -s; }            // even row: (cos, -sin)
        if (row & 2u) { pv.z = a; pv.w = b; }       // pair at lanes 2,3
        else          { pv.x = a; pv.y = b; }       // pair at lanes 0,1
    }

    // ---- 2 unconditional streaming zero stores + 1 predicated overwrite ----
    const float4 z = make_float4(0.f, 0.f, 0.f, 0.f);
    float4* base = out + (size_t)bs * 1024u + tid;
    __stcs(base,        z);                         // slot tid
    __stcs(base + 512u, z);                         // slot tid + 512
    if (match)
        __stcs(base + 512u * km, pv);               // same addr, ordered after zero
}

extern "C" void kernel_launch(void* const* d_in, const int* in_sizes, int n_in,
                              void* d_out, int out_size)
{
    const float* spa = (const float*)d_in[0];
    float4* out = (float4*)d_out;

    unsigned n_mat = (unsigned)(out_size / 4096);   // 16384
    rope2d_kernel<<<n_mat, THREADS>>>(spa, out);
}